// round 2
// baseline (speedup 1.0000x reference)
#include <cuda_runtime.h>

#define N_NODES 50000
#define N_EDGES 800000
#define DIN     64
#define DH      128
#define EPSI    1e-5f
#define SLOPE   0.1f

// ---------------- scratch (device globals; no allocations) ----------------
__device__ float g_deg [N_NODES];
__device__ float g_dinv[N_NODES];
__device__ float g_h   [N_NODES * DH];   // linear-transform output
__device__ float g_agg [N_NODES * DH];   // aggregated messages
__device__ float g_res [N_NODES * DH];   // residual projection
__device__ float g_act [N_NODES * DH];   // post-activation layer output
__device__ float g_stats[2 * DH];        // [0:128) colsum, [128:256) colsumsq
__device__ float g_ab   [2 * DH];        // [0:128) scale a, [128:256) shift c

// ---------------- degree ----------------
__global__ void deg_init_kernel() {
    int i = blockIdx.x * blockDim.x + threadIdx.x;
    if (i < N_NODES) g_deg[i] = 1.0f;   // self-loop weight
}

__global__ void deg_accum_kernel(const int* __restrict__ dst,
                                 const float* __restrict__ ew) {
    int e = blockIdx.x * blockDim.x + threadIdx.x;
    if (e < N_EDGES) atomicAdd(&g_deg[dst[e]], ew[e]);
}

__global__ void dinv_kernel() {
    int i = blockIdx.x * blockDim.x + threadIdx.x;
    if (i < N_NODES) {
        float d = g_deg[i];
        g_dinv[i] = d > 0.0f ? rsqrtf(d) : 0.0f;
    }
}

// ---------------- SGEMM: C[M,128] = A[M,K] @ B[K,128] (+bias) ----------------
// 128x128 block tile, BK=8, 256 threads, 8x8 register microtile per thread.
template <int K>
__global__ __launch_bounds__(256)
void sgemm_kernel(const float* __restrict__ A, const float* __restrict__ B,
                  const float* __restrict__ bias, float* __restrict__ C, int M) {
    __shared__ float As[8][128];
    __shared__ float Bs[8][128];

    int tid = threadIdx.x;
    int tx = tid & 15;        // 0..15 -> col group
    int ty = tid >> 4;        // 0..15 -> row group
    int rowBase = blockIdx.x * 128;

    float acc[8][8];
    #pragma unroll
    for (int i = 0; i < 8; i++)
        #pragma unroll
        for (int j = 0; j < 8; j++) acc[i][j] = 0.0f;

    int aRow = tid >> 1;            // 0..127
    int aCol = (tid & 1) * 4;       // 0 or 4
    int bRow = tid >> 5;            // 0..7
    int bCol = (tid & 31) * 4;      // 0..124

    for (int k0 = 0; k0 < K; k0 += 8) {
        float4 av = make_float4(0.f, 0.f, 0.f, 0.f);
        int gr = rowBase + aRow;
        if (gr < M) av = *(const float4*)(A + (long)gr * K + k0 + aCol);
        As[aCol + 0][aRow] = av.x;
        As[aCol + 1][aRow] = av.y;
        As[aCol + 2][aRow] = av.z;
        As[aCol + 3][aRow] = av.w;
        *(float4*)(&Bs[bRow][bCol]) = *(const float4*)(B + (k0 + bRow) * DH + bCol);
        __syncthreads();

        #pragma unroll
        for (int k = 0; k < 8; k++) {
            float a_frag[8], b_frag[8];
            #pragma unroll
            for (int i = 0; i < 8; i++) a_frag[i] = As[k][ty * 8 + i];
            #pragma unroll
            for (int j = 0; j < 8; j++) b_frag[j] = Bs[k][tx * 8 + j];
            #pragma unroll
            for (int i = 0; i < 8; i++)
                #pragma unroll
                for (int j = 0; j < 8; j++)
                    acc[i][j] += a_frag[i] * b_frag[j];
        }
        __syncthreads();
    }

    #pragma unroll
    for (int i = 0; i < 8; i++) {
        int r = rowBase + ty * 8 + i;
        if (r < M) {
            #pragma unroll
            for (int j = 0; j < 8; j += 4) {
                int c = tx * 8 + j;
                float4 v = make_float4(acc[i][j], acc[i][j+1], acc[i][j+2], acc[i][j+3]);
                if (bias) {
                    v.x += bias[c]; v.y += bias[c+1]; v.z += bias[c+2]; v.w += bias[c+3];
                }
                *(float4*)(C + (long)r * DH + c) = v;
            }
        }
    }
}

// ---------------- agg init: self-loop contribution + bias ----------------
// agg[i,:] = dinv[i]^2 * h[i,:] + b[:]
__global__ void agg_init_kernel(const float* __restrict__ h,
                                const float* __restrict__ bias,
                                float* __restrict__ agg) {
    int idx = blockIdx.x * blockDim.x + threadIdx.x;   // over N*32 float4s
    if (idx >= N_NODES * 32) return;
    int node = idx >> 5;
    int lane = idx & 31;
    float di = g_dinv[node];
    float coef = di * di;
    float4 v = ((const float4*)h)[idx];
    float4 b = ((const float4*)bias)[lane];
    float4 o;
    o.x = coef * v.x + b.x;
    o.y = coef * v.y + b.y;
    o.z = coef * v.z + b.z;
    o.w = coef * v.w + b.w;
    ((float4*)agg)[idx] = o;
}

// ---------------- edge scatter: warp per edge, 4 floats per lane ----------------
__global__ void scatter_kernel(const int* __restrict__ src,
                               const int* __restrict__ dst,
                               const float* __restrict__ ew,
                               const float* __restrict__ h,
                               float* __restrict__ agg) {
    long idx = (long)blockIdx.x * blockDim.x + threadIdx.x;
    long e = idx >> 5;
    int lane = (int)(idx & 31);
    if (e >= N_EDGES) return;
    int s = src[e];
    int d = dst[e];
    float coef = g_dinv[s] * ew[e] * g_dinv[d];
    float4 v = ((const float4*)h)[(long)s * 32 + lane];
    float* out = agg + (long)d * DH + lane * 4;
    atomicAdd(out + 0, coef * v.x);
    atomicAdd(out + 1, coef * v.y);
    atomicAdd(out + 2, coef * v.z);
    atomicAdd(out + 3, coef * v.w);
}

// ---------------- BN stats ----------------
__global__ void zero_stats_kernel() {
    int t = threadIdx.x;
    if (t < 2 * DH) g_stats[t] = 0.0f;
}

__global__ void colstats_kernel(const float* __restrict__ h) {
    int t = threadIdx.x;   // column, blockDim = 128
    int rowsPer = (N_NODES + gridDim.x - 1) / gridDim.x;
    int r0 = blockIdx.x * rowsPer;
    int r1 = min(r0 + rowsPer, N_NODES);
    float s = 0.0f, s2 = 0.0f;
    for (int r = r0; r < r1; r++) {
        float v = h[(long)r * DH + t];
        s += v;
        s2 += v * v;
    }
    atomicAdd(&g_stats[t], s);
    atomicAdd(&g_stats[DH + t], s2);
}

__global__ void bn_finalize_kernel(const float* __restrict__ gamma,
                                   const float* __restrict__ beta) {
    int t = threadIdx.x;
    if (t >= DH) return;
    float invN = 1.0f / (float)N_NODES;
    float mean = g_stats[t] * invN;
    float var  = g_stats[DH + t] * invN - mean * mean;
    float a = gamma[t] * rsqrtf(var + EPSI);
    g_ab[t]      = a;
    g_ab[DH + t] = beta[t] - mean * a;
}

// ---------------- layer-0 epilogue: BN apply + leaky + residual ----------------
__global__ void act_kernel(const float* __restrict__ agg,
                           const float* __restrict__ res,
                           float* __restrict__ out) {
    int idx = blockIdx.x * blockDim.x + threadIdx.x;   // over N*32 float4s
    if (idx >= N_NODES * 32) return;
    int lane = idx & 31;
    float4 a4 = ((const float4*)g_ab)[lane];
    float4 c4 = ((const float4*)g_ab)[32 + lane];
    float4 v = ((const float4*)agg)[idx];
    float4 r = ((const float4*)res)[idx];
    float4 o;
    o.x = a4.x * v.x + c4.x; o.x = (o.x >= 0.f ? o.x : SLOPE * o.x) + r.x;
    o.y = a4.y * v.y + c4.y; o.y = (o.y >= 0.f ? o.y : SLOPE * o.y) + r.y;
    o.z = a4.z * v.z + c4.z; o.z = (o.z >= 0.f ? o.z : SLOPE * o.z) + r.z;
    o.w = a4.w * v.w + c4.w; o.w = (o.w >= 0.f ? o.w : SLOPE * o.w) + r.w;
    ((float4*)out)[idx] = o;
}

// ---------------- layer-1 epilogue fused with final LayerNorm ----------------
// warp per row: BN apply + leaky + residual, then row mean/var + normalize.
__global__ void act_ln_kernel(const float* __restrict__ agg,
                              const float* __restrict__ res,
                              float* __restrict__ out) {
    int row = blockIdx.x * (blockDim.x >> 5) + (threadIdx.x >> 5);
    int lane = threadIdx.x & 31;
    if (row >= N_NODES) return;
    long idx = (long)row * 32 + lane;
    float4 a4 = ((const float4*)g_ab)[lane];
    float4 c4 = ((const float4*)g_ab)[32 + lane];
    float4 v = ((const float4*)agg)[idx];
    float4 r = ((const float4*)res)[idx];
    float4 o;
    o.x = a4.x * v.x + c4.x; o.x = (o.x >= 0.f ? o.x : SLOPE * o.x) + r.x;
    o.y = a4.y * v.y + c4.y; o.y = (o.y >= 0.f ? o.y : SLOPE * o.y) + r.y;
    o.z = a4.z * v.z + c4.z; o.z = (o.z >= 0.f ? o.z : SLOPE * o.z) + r.z;
    o.w = a4.w * v.w + c4.w; o.w = (o.w >= 0.f ? o.w : SLOPE * o.w) + r.w;

    float s  = o.x + o.y + o.z + o.w;
    float s2 = o.x * o.x + o.y * o.y + o.z * o.z + o.w * o.w;
    #pragma unroll
    for (int off = 16; off > 0; off >>= 1) {
        s  += __shfl_xor_sync(0xffffffffu, s,  off);
        s2 += __shfl_xor_sync(0xffffffffu, s2, off);
    }
    float mean = s * (1.0f / DH);
    float var  = s2 * (1.0f / DH) - mean * mean;
    float inv = rsqrtf(var + EPSI);
    float4 w;
    w.x = (o.x - mean) * inv;
    w.y = (o.y - mean) * inv;
    w.z = (o.z - mean) * inv;
    w.w = (o.w - mean) * inv;
    ((float4*)out)[idx] = w;
}

// ---------------- launch ----------------
extern "C" void kernel_launch(void* const* d_in, const int* in_sizes, int n_in,
                              void* d_out, int out_size) {
    const float* x    = (const float*)d_in[0];
    const int*   src  = (const int*)  d_in[1];
    const int*   dst  = (const int*)  d_in[2];
    const float* ew   = (const float*)d_in[3];
    const float* W0   = (const float*)d_in[4];
    const float* b0   = (const float*)d_in[5];
    const float* g0   = (const float*)d_in[6];
    const float* be0  = (const float*)d_in[7];
    const float* W1   = (const float*)d_in[8];
    const float* b1   = (const float*)d_in[9];
    const float* g1   = (const float*)d_in[10];
    const float* be1  = (const float*)d_in[11];
    const float* Wres = (const float*)d_in[12];
    const float* bres = (const float*)d_in[13];
    float* out = (float*)d_out;

    float *gh, *gagg, *gres, *gact;
    cudaGetSymbolAddress((void**)&gh,   g_h);
    cudaGetSymbolAddress((void**)&gagg, g_agg);
    cudaGetSymbolAddress((void**)&gres, g_res);
    cudaGetSymbolAddress((void**)&gact, g_act);

    const int nodeBlocks = (N_NODES + 255) / 256;
    const int edgeBlocks = (N_EDGES + 255) / 256;
    const int vecBlocks  = (N_NODES * 32 + 255) / 256;       // N*32 float4 elems
    const long scatterThreads = (long)N_EDGES * 32;
    const int scatterBlocks = (int)((scatterThreads + 255) / 256);
    const int gemmBlocks = (N_NODES + 127) / 128;            // 391
    const int lnBlocks = (N_NODES + 7) / 8;                  // 8 warps/block

    // degree + normalization (shared by both layers)
    deg_init_kernel<<<nodeBlocks, 256>>>();
    deg_accum_kernel<<<edgeBlocks, 256>>>(dst, ew);
    dinv_kernel<<<nodeBlocks, 256>>>();

    // ===== layer 0 =====
    sgemm_kernel<DIN><<<gemmBlocks, 256>>>(x, W0, nullptr, gh, N_NODES);
    sgemm_kernel<DIN><<<gemmBlocks, 256>>>(x, Wres, bres, gres, N_NODES);
    agg_init_kernel<<<vecBlocks, 256>>>(gh, b0, gagg);
    scatter_kernel<<<scatterBlocks, 256>>>(src, dst, ew, gh, gagg);
    zero_stats_kernel<<<1, 256>>>();
    colstats_kernel<<<256, 128>>>(gagg);
    bn_finalize_kernel<<<1, 128>>>(g0, be0);
    act_kernel<<<vecBlocks, 256>>>(gagg, gres, gact);

    // ===== layer 1 =====
    sgemm_kernel<DH><<<gemmBlocks, 256>>>(gact, W1, nullptr, gh, N_NODES);
    agg_init_kernel<<<vecBlocks, 256>>>(gh, b1, gagg);
    scatter_kernel<<<scatterBlocks, 256>>>(src, dst, ew, gh, gagg);
    zero_stats_kernel<<<1, 256>>>();
    colstats_kernel<<<256, 128>>>(gagg);
    bn_finalize_kernel<<<1, 128>>>(g1, be1);
    act_ln_kernel<<<lnBlocks, 256>>>(gagg, gres, out);
}

// round 3
// speedup vs baseline: 1.8060x; 1.8060x over previous
#include <cuda_runtime.h>

#define N_NODES 50000
#define N_EDGES 800000
#define DIN     64
#define DH      128
#define EPSI    1e-5f
#define SLOPE   0.1f

// ---------------- scratch (device globals; no allocations) ----------------
__device__ float g_deg   [N_NODES];
__device__ float g_dinv  [N_NODES];
__device__ int   g_count [N_NODES];
__device__ int   g_cursor[N_NODES];
__device__ int   g_off   [N_NODES + 1];
__device__ int   g_csr_src[N_EDGES];
__device__ float g_csr_w  [N_EDGES];
__device__ float g_h   [N_NODES * DH];   // linear-transform output
__device__ float g_agg [N_NODES * DH];   // aggregated messages
__device__ float g_res [N_NODES * DH];   // residual projection
__device__ float g_act [N_NODES * DH];   // post-activation layer output
__device__ float g_stats[2 * DH];        // [0:128) colsum, [128:256) colsumsq
__device__ float g_ab   [2 * DH];        // [0:128) scale a, [128:256) shift c

// ---------------- init: deg=1 (self loop), counts/cursors = 0 ----------------
__global__ void init_kernel() {
    int i = blockIdx.x * blockDim.x + threadIdx.x;
    if (i < N_NODES) {
        g_deg[i] = 1.0f;
        g_count[i] = 0;
        g_cursor[i] = 0;
    }
}

// ---------------- per-edge: weighted degree + integer in-degree count ----------
__global__ void edge_count_kernel(const int* __restrict__ dst,
                                  const float* __restrict__ ew) {
    int e = blockIdx.x * blockDim.x + threadIdx.x;
    if (e < N_EDGES) {
        int d = dst[e];
        atomicAdd(&g_deg[d], ew[e]);
        atomicAdd(&g_count[d], 1);
    }
}

__global__ void dinv_kernel() {
    int i = blockIdx.x * blockDim.x + threadIdx.x;
    if (i < N_NODES) {
        float d = g_deg[i];
        g_dinv[i] = d > 0.0f ? rsqrtf(d) : 0.0f;
    }
}

// ---------------- exclusive scan of counts -> offsets (single block) ----------
__global__ __launch_bounds__(1024)
void scan_kernel() {
    __shared__ int sm[1024];
    int t = threadIdx.x;
    const int CH = (N_NODES + 1023) / 1024;   // 49
    int beg = t * CH;
    int end = min(beg + CH, N_NODES);
    int s = 0;
    for (int i = beg; i < end; i++) s += g_count[i];
    sm[t] = s;
    __syncthreads();
    // Hillis-Steele inclusive scan over 1024 chunk sums
    for (int off = 1; off < 1024; off <<= 1) {
        int u = (t >= off) ? sm[t - off] : 0;
        __syncthreads();
        sm[t] += u;
        __syncthreads();
    }
    int run = sm[t] - s;   // exclusive prefix at chunk start
    for (int i = beg; i < end; i++) {
        g_off[i] = run;
        run += g_count[i];
    }
    if (t == 1023) g_off[N_NODES] = sm[1023];
}

// ---------------- fill CSR: src index + precomputed edge coefficient ----------
__global__ void fill_kernel(const int* __restrict__ src,
                            const int* __restrict__ dst,
                            const float* __restrict__ ew) {
    int e = blockIdx.x * blockDim.x + threadIdx.x;
    if (e >= N_EDGES) return;
    int s = src[e];
    int d = dst[e];
    int pos = g_off[d] + atomicAdd(&g_cursor[d], 1);
    g_csr_src[pos] = s;
    g_csr_w[pos] = g_dinv[s] * ew[e] * g_dinv[d];
}

// ---------------- SGEMM: C[M,128] = A[M,K] @ B[K,128] (+bias) ----------------
template <int K>
__global__ __launch_bounds__(256)
void sgemm_kernel(const float* __restrict__ A, const float* __restrict__ B,
                  const float* __restrict__ bias, float* __restrict__ C, int M) {
    __shared__ float As[8][128];
    __shared__ float Bs[8][128];

    int tid = threadIdx.x;
    int tx = tid & 15;
    int ty = tid >> 4;
    int rowBase = blockIdx.x * 128;

    float acc[8][8];
    #pragma unroll
    for (int i = 0; i < 8; i++)
        #pragma unroll
        for (int j = 0; j < 8; j++) acc[i][j] = 0.0f;

    int aRow = tid >> 1;
    int aCol = (tid & 1) * 4;
    int bRow = tid >> 5;
    int bCol = (tid & 31) * 4;

    for (int k0 = 0; k0 < K; k0 += 8) {
        float4 av = make_float4(0.f, 0.f, 0.f, 0.f);
        int gr = rowBase + aRow;
        if (gr < M) av = *(const float4*)(A + (long)gr * K + k0 + aCol);
        As[aCol + 0][aRow] = av.x;
        As[aCol + 1][aRow] = av.y;
        As[aCol + 2][aRow] = av.z;
        As[aCol + 3][aRow] = av.w;
        *(float4*)(&Bs[bRow][bCol]) = *(const float4*)(B + (k0 + bRow) * DH + bCol);
        __syncthreads();

        #pragma unroll
        for (int k = 0; k < 8; k++) {
            float a_frag[8], b_frag[8];
            #pragma unroll
            for (int i = 0; i < 8; i++) a_frag[i] = As[k][ty * 8 + i];
            #pragma unroll
            for (int j = 0; j < 8; j++) b_frag[j] = Bs[k][tx * 8 + j];
            #pragma unroll
            for (int i = 0; i < 8; i++)
                #pragma unroll
                for (int j = 0; j < 8; j++)
                    acc[i][j] += a_frag[i] * b_frag[j];
        }
        __syncthreads();
    }

    #pragma unroll
    for (int i = 0; i < 8; i++) {
        int r = rowBase + ty * 8 + i;
        if (r < M) {
            #pragma unroll
            for (int j = 0; j < 8; j += 4) {
                int c = tx * 8 + j;
                float4 v = make_float4(acc[i][j], acc[i][j+1], acc[i][j+2], acc[i][j+3]);
                if (bias) {
                    v.x += bias[c]; v.y += bias[c+1]; v.z += bias[c+2]; v.w += bias[c+3];
                }
                *(float4*)(C + (long)r * DH + c) = v;
            }
        }
    }
}

// ---------------- fused aggregation: self-loop + bias + gather-reduce + BN stats
// warp per dst node; lane l owns columns [4l, 4l+4)
__global__ __launch_bounds__(256)
void aggregate_kernel(const float* __restrict__ h,
                      const float* __restrict__ bias,
                      float* __restrict__ agg) {
    __shared__ float s_sum[DH];
    __shared__ float s_sq [DH];
    int tid = threadIdx.x;
    if (tid < DH) { s_sum[tid] = 0.0f; s_sq[tid] = 0.0f; }
    __syncthreads();

    int node = blockIdx.x * 8 + (tid >> 5);        // grid sized exactly N/8
    int lane = tid & 31;
    const float4* h4 = (const float4*)h;

    // self-loop contribution + bias
    float di = g_dinv[node];
    float coef = di * di;
    float4 b = ((const float4*)bias)[lane];
    float4 v0 = h4[(long)node * 32 + lane];
    float4 acc;
    acc.x = coef * v0.x + b.x;
    acc.y = coef * v0.y + b.y;
    acc.z = coef * v0.z + b.z;
    acc.w = coef * v0.w + b.w;

    int beg = g_off[node];
    int end = g_off[node + 1];
    for (int j0 = beg; j0 < end; j0 += 32) {
        int j = j0 + lane;
        int   es = 0;
        float ew = 0.0f;
        if (j < end) { es = g_csr_src[j]; ew = g_csr_w[j]; }
        int cnt = min(32, end - j0);
        for (int i = 0; i < cnt; i++) {
            int   ss = __shfl_sync(0xffffffffu, es, i);
            float ww = __shfl_sync(0xffffffffu, ew, i);
            float4 v = h4[(long)ss * 32 + lane];
            acc.x += ww * v.x;
            acc.y += ww * v.y;
            acc.z += ww * v.z;
            acc.w += ww * v.w;
        }
    }

    ((float4*)agg)[(long)node * 32 + lane] = acc;

    // fused BN column stats: block-level shared reduction, then global atomics
    int c = lane * 4;
    atomicAdd(&s_sum[c + 0], acc.x);
    atomicAdd(&s_sum[c + 1], acc.y);
    atomicAdd(&s_sum[c + 2], acc.z);
    atomicAdd(&s_sum[c + 3], acc.w);
    atomicAdd(&s_sq [c + 0], acc.x * acc.x);
    atomicAdd(&s_sq [c + 1], acc.y * acc.y);
    atomicAdd(&s_sq [c + 2], acc.z * acc.z);
    atomicAdd(&s_sq [c + 3], acc.w * acc.w);
    __syncthreads();
    if (tid < DH) {
        atomicAdd(&g_stats[tid],      s_sum[tid]);
        atomicAdd(&g_stats[DH + tid], s_sq [tid]);
    }
}

// ---------------- BN stats helpers ----------------
__global__ void zero_stats_kernel() {
    int t = threadIdx.x;
    if (t < 2 * DH) g_stats[t] = 0.0f;
}

__global__ void bn_finalize_kernel(const float* __restrict__ gamma,
                                   const float* __restrict__ beta) {
    int t = threadIdx.x;
    if (t >= DH) return;
    float invN = 1.0f / (float)N_NODES;
    float mean = g_stats[t] * invN;
    float var  = g_stats[DH + t] * invN - mean * mean;
    float a = gamma[t] * rsqrtf(var + EPSI);
    g_ab[t]      = a;
    g_ab[DH + t] = beta[t] - mean * a;
}

// ---------------- layer-0 epilogue: BN apply + leaky + residual ----------------
__global__ void act_kernel(const float* __restrict__ agg,
                           const float* __restrict__ res,
                           float* __restrict__ out) {
    int idx = blockIdx.x * blockDim.x + threadIdx.x;
    if (idx >= N_NODES * 32) return;
    int lane = idx & 31;
    float4 a4 = ((const float4*)g_ab)[lane];
    float4 c4 = ((const float4*)g_ab)[32 + lane];
    float4 v = ((const float4*)agg)[idx];
    float4 r = ((const float4*)res)[idx];
    float4 o;
    o.x = a4.x * v.x + c4.x; o.x = (o.x >= 0.f ? o.x : SLOPE * o.x) + r.x;
    o.y = a4.y * v.y + c4.y; o.y = (o.y >= 0.f ? o.y : SLOPE * o.y) + r.y;
    o.z = a4.z * v.z + c4.z; o.z = (o.z >= 0.f ? o.z : SLOPE * o.z) + r.z;
    o.w = a4.w * v.w + c4.w; o.w = (o.w >= 0.f ? o.w : SLOPE * o.w) + r.w;
    ((float4*)out)[idx] = o;
}

// ---------------- layer-1 epilogue fused with final LayerNorm ----------------
__global__ void act_ln_kernel(const float* __restrict__ agg,
                              const float* __restrict__ res,
                              float* __restrict__ out) {
    int row = blockIdx.x * (blockDim.x >> 5) + (threadIdx.x >> 5);
    int lane = threadIdx.x & 31;
    if (row >= N_NODES) return;
    long idx = (long)row * 32 + lane;
    float4 a4 = ((const float4*)g_ab)[lane];
    float4 c4 = ((const float4*)g_ab)[32 + lane];
    float4 v = ((const float4*)agg)[idx];
    float4 r = ((const float4*)res)[idx];
    float4 o;
    o.x = a4.x * v.x + c4.x; o.x = (o.x >= 0.f ? o.x : SLOPE * o.x) + r.x;
    o.y = a4.y * v.y + c4.y; o.y = (o.y >= 0.f ? o.y : SLOPE * o.y) + r.y;
    o.z = a4.z * v.z + c4.z; o.z = (o.z >= 0.f ? o.z : SLOPE * o.z) + r.z;
    o.w = a4.w * v.w + c4.w; o.w = (o.w >= 0.f ? o.w : SLOPE * o.w) + r.w;

    float s  = o.x + o.y + o.z + o.w;
    float s2 = o.x * o.x + o.y * o.y + o.z * o.z + o.w * o.w;
    #pragma unroll
    for (int off = 16; off > 0; off >>= 1) {
        s  += __shfl_xor_sync(0xffffffffu, s,  off);
        s2 += __shfl_xor_sync(0xffffffffu, s2, off);
    }
    float mean = s * (1.0f / DH);
    float var  = s2 * (1.0f / DH) - mean * mean;
    float inv = rsqrtf(var + EPSI);
    float4 w;
    w.x = (o.x - mean) * inv;
    w.y = (o.y - mean) * inv;
    w.z = (o.z - mean) * inv;
    w.w = (o.w - mean) * inv;
    ((float4*)out)[idx] = w;
}

// ---------------- launch ----------------
extern "C" void kernel_launch(void* const* d_in, const int* in_sizes, int n_in,
                              void* d_out, int out_size) {
    const float* x    = (const float*)d_in[0];
    const int*   src  = (const int*)  d_in[1];
    const int*   dst  = (const int*)  d_in[2];
    const float* ew   = (const float*)d_in[3];
    const float* W0   = (const float*)d_in[4];
    const float* b0   = (const float*)d_in[5];
    const float* g0   = (const float*)d_in[6];
    const float* be0  = (const float*)d_in[7];
    const float* W1   = (const float*)d_in[8];
    const float* b1   = (const float*)d_in[9];
    const float* g1   = (const float*)d_in[10];
    const float* be1  = (const float*)d_in[11];
    const float* Wres = (const float*)d_in[12];
    const float* bres = (const float*)d_in[13];
    float* out = (float*)d_out;

    float *gh, *gagg, *gres, *gact;
    cudaGetSymbolAddress((void**)&gh,   g_h);
    cudaGetSymbolAddress((void**)&gagg, g_agg);
    cudaGetSymbolAddress((void**)&gres, g_res);
    cudaGetSymbolAddress((void**)&gact, g_act);

    const int nodeBlocks = (N_NODES + 255) / 256;
    const int edgeBlocks = (N_EDGES + 255) / 256;
    const int vecBlocks  = (N_NODES * 32 + 255) / 256;
    const int gemmBlocks = (N_NODES + 127) / 128;
    const int aggBlocks  = N_NODES / 8;               // 6250, exact
    const int lnBlocks   = (N_NODES + 7) / 8;

    // ---- CSR build (shared by both layers) ----
    init_kernel<<<nodeBlocks, 256>>>();
    edge_count_kernel<<<edgeBlocks, 256>>>(dst, ew);
    dinv_kernel<<<nodeBlocks, 256>>>();
    scan_kernel<<<1, 1024>>>();
    fill_kernel<<<edgeBlocks, 256>>>(src, dst, ew);

    // ===== layer 0 =====
    sgemm_kernel<DIN><<<gemmBlocks, 256>>>(x, W0, nullptr, gh, N_NODES);
    sgemm_kernel<DIN><<<gemmBlocks, 256>>>(x, Wres, bres, gres, N_NODES);
    zero_stats_kernel<<<1, 256>>>();
    aggregate_kernel<<<aggBlocks, 256>>>(gh, b0, gagg);
    bn_finalize_kernel<<<1, 128>>>(g0, be0);
    act_kernel<<<vecBlocks, 256>>>(gagg, gres, gact);

    // ===== layer 1 =====
    sgemm_kernel<DH><<<gemmBlocks, 256>>>(gact, W1, nullptr, gh, N_NODES);
    zero_stats_kernel<<<1, 256>>>();
    aggregate_kernel<<<aggBlocks, 256>>>(gh, b1, gagg);
    bn_finalize_kernel<<<1, 128>>>(g1, be1);
    act_ln_kernel<<<lnBlocks, 256>>>(gagg, gres, out);
}